// round 14
// baseline (speedup 1.0000x reference)
#include <cuda_runtime.h>
#include <cstdint>

#define NN   1024
#define DIM  128
#define NH   8
#define ED   16

#define BN   8      // target rows per CTA (4 warps x 2 rows)
#define BM   32     // source nodes per tile (one per lane)
#define KPAD 132    // k/v smem row stride (floats): conflict-free per-lane rows
#define EFPAD 20    // ef smem row stride (floats)
#define PSTR 68     // p smem per-(row,head) stride (floats): 64 dup-pairs + pad, 16B-mult

// ---- attn smem layout (floats) ----
#define OQ    0
#define OWAE  (OQ   + BN*DIM)            // 1024
#define OS    (OWAE + ED*NH)             // 1152
#define OK0   (OS   + BN*DIM)            // 2176
#define OK1   (OK0  + BM*KPAD)           // 6400
#define OV0   (OK1  + BM*KPAD)           // 10624
#define OV1   (OV0  + BM*KPAD)           // 14848
#define OE0   (OV1  + BM*KPAD)           // 19072
#define OE1   (OE0  + BN*BM*EFPAD)       // 24192
#define OP    (OE1  + BN*BM*EFPAD)       // 29312
#define SMEM_FLOATS (OP + BN*NH*PSTR)    // 33664
#define SMEM_BYTES  (SMEM_FLOATS * 4)    // 134656

typedef unsigned long long u64;

__device__ __align__(16) float g_q[NN*DIM];
__device__ __align__(16) float g_k[NN*DIM];
__device__ __align__(16) float g_v[NN*DIM];
__device__ __align__(16) float g_att[NN*DIM];

__device__ __forceinline__ void cpa16(uint32_t dst, const void* src) {
    asm volatile("cp.async.cg.shared.global [%0], [%1], 16;\n" :: "r"(dst), "l"(src));
}
__device__ __forceinline__ void cp_commit() { asm volatile("cp.async.commit_group;\n"); }
__device__ __forceinline__ void cp_wait0()  { asm volatile("cp.async.wait_group 0;\n"); }

// ---- packed f32x2 helpers (FFMA2: ptxas never auto-fuses; PTX-only) ----
__device__ __forceinline__ u64 ffma2(u64 a, u64 b, u64 c) {
    u64 d;
    asm("fma.rn.f32x2 %0, %1, %2, %3;" : "=l"(d) : "l"(a), "l"(b), "l"(c));
    return d;
}
__device__ __forceinline__ u64 pack2(float lo, float hi) {
    u64 d; asm("mov.b64 %0, {%1, %2};" : "=l"(d) : "f"(lo), "f"(hi)); return d;
}
__device__ __forceinline__ void unpack2(u64 v, float& lo, float& hi) {
    asm("mov.b64 {%0, %1}, %2;" : "=f"(lo), "=f"(hi) : "l"(v));
}
union F4U2 { float4 f; u64 d[2]; };

// ---------------------------------------------------------------------------
// Kernel 1: pre-LayerNorm + Q/K/V projections.
// grid 256 (4 rows/CTA), block 384: warps 0-3 LN the 4 rows; then warpgroup g
// (threads [128g,128g+128)) computes projection g (0=q,1=k,2=v) for 4 rows.
// q pre-scaled by 1/sqrt(dk) = 0.25
// ---------------------------------------------------------------------------
__global__ void __launch_bounds__(384) ln_qkv_kernel(const float* __restrict__ x,
    const float* __restrict__ Wq, const float* __restrict__ bq,
    const float* __restrict__ Wk, const float* __restrict__ bk,
    const float* __restrict__ Wv, const float* __restrict__ bv,
    const float* __restrict__ gamma, const float* __restrict__ beta)
{
    __shared__ float hs[4][DIM];
    const int t = threadIdx.x;
    const int lane = t & 31, wid = t >> 5;
    const int r0 = blockIdx.x * 4;

    if (wid < 4) {                       // one warp per row: LN
        const int r = wid;
        float xv[4], s = 0.f, s2 = 0.f;
        #pragma unroll
        for (int j = 0; j < 4; j++) {
            xv[j] = x[(r0 + r) * DIM + lane + j * 32];
            s += xv[j]; s2 += xv[j] * xv[j];
        }
        #pragma unroll
        for (int o = 16; o; o >>= 1) {
            s  += __shfl_xor_sync(0xffffffffu, s,  o);
            s2 += __shfl_xor_sync(0xffffffffu, s2, o);
        }
        float mu   = s * (1.0f / DIM);
        float var  = s2 * (1.0f / DIM) - mu * mu;
        float rstd = rsqrtf(var + 1e-5f);
        #pragma unroll
        for (int j = 0; j < 4; j++) {
            int c = lane + j * 32;
            hs[r][c] = (xv[j] - mu) * rstd * gamma[c] + beta[c];
        }
    }
    __syncthreads();

    const int g = t >> 7;                // 0=q, 1=k, 2=v
    const int c = t & 127;
    const float* W = (g == 0) ? Wq : (g == 1) ? Wk : Wv;
    const float* B = (g == 0) ? bq : (g == 1) ? bk : bv;
    float* O       = (g == 0) ? g_q : (g == 1) ? g_k : g_v;

    float acc[4];
    #pragma unroll
    for (int r = 0; r < 4; r++) acc[r] = 0.f;

    #pragma unroll 8
    for (int k = 0; k < DIM; k += 4) {
        float w0 = W[(k+0)*DIM + c];
        float w1 = W[(k+1)*DIM + c];
        float w2 = W[(k+2)*DIM + c];
        float w3 = W[(k+3)*DIM + c];
        #pragma unroll
        for (int r = 0; r < 4; r++) {
            float4 hv = *(const float4*)&hs[r][k];
            acc[r] += hv.x*w0 + hv.y*w1 + hv.z*w2 + hv.w*w3;
        }
    }
    const float bb = B[c];
    const float sc = (g == 0) ? 0.25f : 1.0f;
    #pragma unroll
    for (int r = 0; r < 4; r++)
        O[(r0 + r) * DIM + c] = (acc[r] + bb) * sc;
}

// ---------------------------------------------------------------------------
// Kernel 2: fused edge-biased attention, softmax-free, packed f32x2 math.
// grid 128, block 128 (4 warps). Warp w owns rows nA=nb+2w, nB=nb+2w+1.
// p stored in smem as duplicated (p,p) pairs so the accumulate loop loads
// ready-packed f32x2 operands via broadcast reads. k/v/ef double-buffered
// through cp.async.
// ---------------------------------------------------------------------------
__global__ void __launch_bounds__(128, 1) attn_kernel(
    const float* __restrict__ ef, const int* __restrict__ mask,
    const float* __restrict__ Wae, const float* __restrict__ bae,
    const float* __restrict__ Wve, const float* __restrict__ bve)
{
    extern __shared__ float sm[];
    float* q_s   = sm + OQ;
    float* wae_s = sm + OWAE;
    float* s_s   = sm + OS;
    float* p_s   = sm + OP;

    const int t = threadIdx.x;
    const int l = t & 31, w = t >> 5;
    const int nb = blockIdx.x * BN;
    const int rA = 2*w, rB = 2*w + 1;
    const int nA = nb + rA, nB = nb + rB;

    uint32_t smem_u32 = (uint32_t)__cvta_generic_to_shared(sm);

    // one-time loads
    for (int i = t; i < BN*DIM; i += 128) q_s[i] = g_q[nb*DIM + i];
    for (int i = t; i < ED*NH;  i += 128) wae_s[i] = Wae[i];

    u64 baeh[8];                    // (bae[h], 0) — folded into qk chain init
    #pragma unroll
    for (int h = 0; h < 8; h++) baeh[h] = pack2(__ldg(&bae[h]), 0.f);

    // ---- tile staging via cp.async ----
    auto stage = [&](int m0, int buf) {
        const float* ksrc = g_k + m0 * DIM;
        const float* vsrc = g_v + m0 * DIM;
        uint32_t kd = smem_u32 + (uint32_t)(buf ? OK1 : OK0) * 4u;
        uint32_t vd = smem_u32 + (uint32_t)(buf ? OV1 : OV0) * 4u;
        #pragma unroll
        for (int j = 0; j < 8; j++) {
            int ch = t + j * 128;            // 0..1023 float4-chunks
            int row = ch >> 5, c4 = ch & 31;
            uint32_t off = (uint32_t)(row * KPAD + c4 * 4) * 4u;
            cpa16(kd + off, ksrc + row * DIM + c4 * 4);
            cpa16(vd + off, vsrc + row * DIM + c4 * 4);
        }
        uint32_t ed = smem_u32 + (uint32_t)(buf ? OE1 : OE0) * 4u;
        #pragma unroll
        for (int j = 0; j < 8; j++) {
            int ch = t + j * 128;
            int r = ch >> 7, c = ch & 127;   // c = m*4 + e4
            int mi = c >> 2, e4 = c & 3;
            cpa16(ed + (uint32_t)((r * BM + mi) * EFPAD + e4 * 4) * 4u,
                  ef + ((size_t)(nb + r) * NN + m0 + mi) * ED + e4 * 4);
        }
    };

    stage(0, 0);
    cp_commit();

    float run_lA[8], run_lB[8];
    #pragma unroll
    for (int h = 0; h < 8; h++) { run_lA[h] = 0.f; run_lB[h] = 0.f; }
    u64 accvA[2] = {0ull, 0ull}, accsA[2] = {0ull, 0ull};
    u64 accvB[2] = {0ull, 0ull}, accsB[2] = {0ull, 0ull};

    const int h4 = l >> 2;          // head owned by this lane's accumulators
    const int e0 = (l & 3) * 4;     // edge-feature sub-range for accs

    const int* mrowA = mask + (size_t)nA * NN;
    const int* mrowB = mask + (size_t)nB * NN;
    const u64* qA2 = (const u64*)(q_s + rA * DIM);   // 64 packed dim-pairs
    const u64* qB2 = (const u64*)(q_s + rB * DIM);
    const u64* wae2 = (const u64*)wae_s;             // [e*4 + headpair]

    cp_wait0();
    __syncthreads();   // tile 0 + q_s/wae_s ready

    for (int mt = 0; mt < NN / BM; mt++) {
        const int m0 = mt * BM;
        const int cur = mt & 1;
        float* k_s  = sm + (cur ? OK1 : OK0);
        float* v_s  = sm + (cur ? OV1 : OV0);
        float* ef_s = sm + (cur ? OE1 : OE0);

        if (mt + 1 < NN / BM) { stage(m0 + BM, cur ^ 1); cp_commit(); }

        const int mA = mrowA[m0 + l];
        const int mB = mrowB[m0 + l];

        // ---- qk logits for m = m0 + l, both rows, packed over dim-pairs ----
        float sA[8], sB[8];
        {
            const u64* kv2 = (const u64*)(k_s + l * KPAD);
            #pragma unroll
            for (int h = 0; h < 8; h++) {
                u64 aA = baeh[h], aB = baeh[h];
                #pragma unroll
                for (int j = 0; j < 8; j++) {
                    u64 kk = kv2[h*8 + j];
                    aA = ffma2(qA2[h*8 + j], kk, aA);
                    aB = ffma2(qB2[h*8 + j], kk, aB);
                }
                float lo, hi;
                unpack2(aA, lo, hi); sA[h] = lo + hi;
                unpack2(aB, lo, hi); sB[h] = lo + hi;
            }
        }
        // ---- edge bias: ef[n,m,:] @ Wae, packed over head-pairs ----
        u64 lgA2[4], lgB2[4];
        #pragma unroll
        for (int hp = 0; hp < 4; hp++) {
            lgA2[hp] = pack2(sA[2*hp], sA[2*hp+1]);
            lgB2[hp] = pack2(sB[2*hp], sB[2*hp+1]);
        }
        {
            const float4* efA = (const float4*)(ef_s + (rA*BM + l) * EFPAD);
            const float4* efB = (const float4*)(ef_s + (rB*BM + l) * EFPAD);
            float4 a4[4], b4[4];
            a4[0]=efA[0]; a4[1]=efA[1]; a4[2]=efA[2]; a4[3]=efA[3];
            b4[0]=efB[0]; b4[1]=efB[1]; b4[2]=efB[2]; b4[3]=efB[3];
            const float* ea = (const float*)a4;
            const float* eb = (const float*)b4;
            #pragma unroll
            for (int e = 0; e < 16; e++) {
                u64 va2 = pack2(ea[e], ea[e]);
                u64 vb2 = pack2(eb[e], eb[e]);
                #pragma unroll
                for (int hp = 0; hp < 4; hp++) {
                    u64 wv = wae2[e*4 + hp];
                    lgA2[hp] = ffma2(va2, wv, lgA2[hp]);
                    lgB2[hp] = ffma2(vb2, wv, lgB2[hp]);
                }
            }
        }

        // ---- p = exp(logit) (0 if masked); store duplicated (p,p) pairs ----
        #pragma unroll
        for (int hp = 0; hp < 4; hp++) {
            float a0, a1, b0, b1;
            unpack2(lgA2[hp], a0, a1);
            unpack2(lgB2[hp], b0, b1);
            float pA0 = mA ? __expf(a0) : 0.f;
            float pA1 = mA ? __expf(a1) : 0.f;
            float pB0 = mB ? __expf(b0) : 0.f;
            float pB1 = mB ? __expf(b1) : 0.f;
            *(float2*)(p_s + (rA*NH + 2*hp+0) * PSTR + 2*l) = make_float2(pA0, pA0);
            *(float2*)(p_s + (rA*NH + 2*hp+1) * PSTR + 2*l) = make_float2(pA1, pA1);
            *(float2*)(p_s + (rB*NH + 2*hp+0) * PSTR + 2*l) = make_float2(pB0, pB0);
            *(float2*)(p_s + (rB*NH + 2*hp+1) * PSTR + 2*l) = make_float2(pB1, pB1);
            run_lA[2*hp+0] += pA0; run_lA[2*hp+1] += pA1;
            run_lB[2*hp+0] += pB0; run_lB[2*hp+1] += pB1;
        }
        __syncwarp();

        // ---- accumulate: packed column-pairs, p pre-packed (broadcast) ----
        const float4* pA4 = (const float4*)(p_s + (rA*NH + h4) * PSTR);
        const float4* pB4 = (const float4*)(p_s + (rB*NH + h4) * PSTR);
        #pragma unroll
        for (int g2 = 0; g2 < 16; g2++) {     // 2 source nodes per iter
            F4U2 pa; pa.f = pA4[g2];           // (p0,p0,p1,p1)
            F4U2 pb; pb.f = pB4[g2];
            #pragma unroll
            for (int j = 0; j < 2; j++) {
                int mm = 2*g2 + j;
                u64 paj = pa.d[j], pbj = pb.d[j];
                F4U2 vv; vv.f = *(const float4*)(v_s + mm*KPAD + 4*l);
                F4U2 eA; eA.f = *(const float4*)(ef_s + (rA*BM + mm)*EFPAD + e0);
                F4U2 eB; eB.f = *(const float4*)(ef_s + (rB*BM + mm)*EFPAD + e0);
                accvA[0] = ffma2(paj, vv.d[0], accvA[0]);
                accvA[1] = ffma2(paj, vv.d[1], accvA[1]);
                accvB[0] = ffma2(pbj, vv.d[0], accvB[0]);
                accvB[1] = ffma2(pbj, vv.d[1], accvB[1]);
                accsA[0] = ffma2(paj, eA.d[0], accsA[0]);
                accsA[1] = ffma2(paj, eA.d[1], accsA[1]);
                accsB[0] = ffma2(pbj, eB.d[0], accsB[0]);
                accsB[1] = ffma2(pbj, eB.d[1], accsB[1]);
            }
        }

        if (mt + 1 < NN / BM) cp_wait0();
        __syncthreads();   // all warps done with cur tile; next tile landed
    }

    // ---- final denominators: warp-reduce per head, both rows ----
    #pragma unroll
    for (int h = 0; h < 8; h++) {
        float sa = run_lA[h], sb = run_lB[h];
        #pragma unroll
        for (int o = 16; o; o >>= 1) {
            sa += __shfl_xor_sync(0xffffffffu, sa, o);
            sb += __shfl_xor_sync(0xffffffffu, sb, o);
        }
        run_lA[h] = sa; run_lB[h] = sb;
    }
    float4 avA, asA, avB, asB;
    {
        float iA = 1.0f / run_lA[h4];
        float iB = 1.0f / run_lB[h4];
        F4U2 u;
        u.d[0] = accvA[0]; u.d[1] = accvA[1]; avA = u.f;
        u.d[0] = accsA[0]; u.d[1] = accsA[1]; asA = u.f;
        u.d[0] = accvB[0]; u.d[1] = accvB[1]; avB = u.f;
        u.d[0] = accsB[0]; u.d[1] = accsB[1]; asB = u.f;
        avA.x *= iA; avA.y *= iA; avA.z *= iA; avA.w *= iA;
        asA.x *= iA; asA.y *= iA; asA.z *= iA; asA.w *= iA;
        avB.x *= iB; avB.y *= iB; avB.z *= iB; avB.w *= iB;
        asB.x *= iB; asB.y *= iB; asB.z *= iB; asB.w *= iB;
    }
    // Shat[h][e] at column h*16+e == 4l (warp-private rows -> syncwarp only)
    *(float4*)(s_s + rA*DIM + 4*l) = asA;
    *(float4*)(s_s + rB*DIM + 4*l) = asB;
    __syncwarp();

    float4 oA = avA, oB = avB;
    {
        float4 b4 = *(const float4*)(bve + 4*l);
        oA.x += b4.x; oA.y += b4.y; oA.z += b4.z; oA.w += b4.w;
        oB.x += b4.x; oB.y += b4.y; oB.z += b4.z; oB.w += b4.w;
    }
    #pragma unroll
    for (int e = 0; e < 16; e++) {
        float sA = s_s[rA*DIM + h4*16 + e];
        float sB = s_s[rB*DIM + h4*16 + e];
        float4 wv = *(const float4*)(Wve + e*DIM + 4*l);
        oA.x += sA*wv.x; oA.y += sA*wv.y; oA.z += sA*wv.z; oA.w += sA*wv.w;
        oB.x += sB*wv.x; oB.y += sB*wv.y; oB.z += sB*wv.z; oB.w += sB*wv.w;
    }
    *(float4*)(g_att + (size_t)nA*DIM + 4*l) = oA;
    *(float4*)(g_att + (size_t)nB*DIM + 4*l) = oB;
}

// ---------------------------------------------------------------------------
// Kernel 3: output projection + residual. grid 256 (4 rows), block 256,
// split-K by 2.
// ---------------------------------------------------------------------------
__global__ void __launch_bounds__(256) out_proj_kernel(const float* __restrict__ x,
    const float* __restrict__ Wo, const float* __restrict__ bo,
    float* __restrict__ out)
{
    __shared__ float as[4][DIM];
    __shared__ float part[4][DIM];
    const int t = threadIdx.x;
    const int c = t & 127, half = t >> 7;
    const int r0 = blockIdx.x * 4;

    for (int i = t; i < 4*DIM; i += 256)
        as[i >> 7][i & 127] = g_att[r0*DIM + i];
    __syncthreads();

    float acc[4];
    #pragma unroll
    for (int r = 0; r < 4; r++) acc[r] = 0.f;

    const int k0 = half * 64;
    #pragma unroll 4
    for (int k = k0; k < k0 + 64; k += 4) {
        float w0 = Wo[(k+0)*DIM + c];
        float w1 = Wo[(k+1)*DIM + c];
        float w2 = Wo[(k+2)*DIM + c];
        float w3 = Wo[(k+3)*DIM + c];
        #pragma unroll
        for (int r = 0; r < 4; r++) {
            float4 hv = *(const float4*)&as[r][k];
            acc[r] += hv.x*w0 + hv.y*w1 + hv.z*w2 + hv.w*w3;
        }
    }
    if (half) {
        #pragma unroll
        for (int r = 0; r < 4; r++) part[r][c] = acc[r];
    }
    __syncthreads();
    if (!half) {
        const float bv = bo[c];
        #pragma unroll
        for (int r = 0; r < 4; r++)
            out[(r0+r)*DIM + c] = x[(r0+r)*DIM + c] + acc[r] + part[r][c] + bv;
    }
}

// ---------------------------------------------------------------------------
extern "C" void kernel_launch(void* const* d_in, const int* in_sizes, int n_in,
                              void* d_out, int out_size)
{
    const float* x    = (const float*)d_in[0];
    const float* ef   = (const float*)d_in[1];
    const int*   mask = (const int*)d_in[2];
    const float* Wq   = (const float*)d_in[3];
    const float* bq   = (const float*)d_in[4];
    const float* Wk   = (const float*)d_in[5];
    const float* bk   = (const float*)d_in[6];
    const float* Wv   = (const float*)d_in[7];
    const float* bv   = (const float*)d_in[8];
    const float* Wae  = (const float*)d_in[9];
    const float* bae  = (const float*)d_in[10];
    const float* Wve  = (const float*)d_in[11];
    const float* bve  = (const float*)d_in[12];
    const float* Wo   = (const float*)d_in[13];
    const float* bo   = (const float*)d_in[14];
    const float* gamma= (const float*)d_in[15];
    const float* beta = (const float*)d_in[16];
    float* out = (float*)d_out;

    cudaFuncSetAttribute(attn_kernel,
        cudaFuncAttributeMaxDynamicSharedMemorySize, SMEM_BYTES);

    ln_qkv_kernel<<<NN/4, 384>>>(x, Wq, bq, Wk, bk, Wv, bv, gamma, beta);
    attn_kernel<<<NN/BN, 128, SMEM_BYTES>>>(ef, mask, Wae, bae, Wve, bve);
    out_proj_kernel<<<NN/4, 256>>>(x, Wo, bo, out);
}

// round 15
// speedup vs baseline: 1.4693x; 1.4693x over previous
#include <cuda_runtime.h>
#include <cstdint>

#define NN   1024
#define DIM  128
#define NH   8
#define ED   16

#define BN   8      // target rows per CTA
#define BM   32     // source nodes per tile (one per lane)
#define KPAD 132    // k/v smem row stride (floats): conflict-free per-lane rows
#define EFPAD 20    // ef smem row stride (floats)
#define PSTR 36     // p smem per-(row,head) stride (floats)

// ---- attn smem layout (floats) ----
#define OQ    0
#define OWAE  (OQ   + BN*DIM)            // 1024
#define OS    (OWAE + ED*NH)             // 1152
#define OK0   (OS   + BN*DIM)            // 2176
#define OK1   (OK0  + BM*KPAD)           // 6400
#define OV0   (OK1  + BM*KPAD)           // 10624
#define OV1   (OV0  + BM*KPAD)           // 14848
#define OE0   (OV1  + BM*KPAD)           // 19072
#define OE1   (OE0  + BN*BM*EFPAD)       // 24192
#define OP    (OE1  + BN*BM*EFPAD)       // 29312
#define SMEM_FLOATS (OP + BN*NH*PSTR)    // 31616
#define SMEM_BYTES  (SMEM_FLOATS * 4)    // 126464

__device__ __align__(16) float g_q[NN*DIM];
__device__ __align__(16) float g_k[NN*DIM];
__device__ __align__(16) float g_v[NN*DIM];
__device__ __align__(16) float g_att[NN*DIM];

__device__ __forceinline__ void cpa16(uint32_t dst, const void* src) {
    asm volatile("cp.async.cg.shared.global [%0], [%1], 16;\n" :: "r"(dst), "l"(src));
}
__device__ __forceinline__ void cp_commit() { asm volatile("cp.async.commit_group;\n"); }
__device__ __forceinline__ void cp_wait0()  { asm volatile("cp.async.wait_group 0;\n"); }

// ---------------------------------------------------------------------------
// Kernel 1: pre-LayerNorm + Q/K/V projections, split-K.
// grid 256 (4 rows/CTA), block 768: warps 0-3 LN the 4 rows; then group
// g = t/256 computes projection g (0=q,1=k,2=v), with each half-warpgroup
// (kh = 0/1) covering half the K dimension. q pre-scaled by 0.25.
// ---------------------------------------------------------------------------
__global__ void __launch_bounds__(768) ln_qkv_kernel(const float* __restrict__ x,
    const float* __restrict__ Wq, const float* __restrict__ bq,
    const float* __restrict__ Wk, const float* __restrict__ bk,
    const float* __restrict__ Wv, const float* __restrict__ bv,
    const float* __restrict__ gamma, const float* __restrict__ beta)
{
    __shared__ float hs[4][DIM];
    __shared__ float part[3][4][DIM];
    const int t = threadIdx.x;
    const int lane = t & 31, wid = t >> 5;
    const int r0 = blockIdx.x * 4;

    if (wid < 4) {                       // one warp per row: LN
        const int r = wid;
        float xv[4], s = 0.f, s2 = 0.f;
        #pragma unroll
        for (int j = 0; j < 4; j++) {
            xv[j] = x[(r0 + r) * DIM + lane + j * 32];
            s += xv[j]; s2 += xv[j] * xv[j];
        }
        #pragma unroll
        for (int o = 16; o; o >>= 1) {
            s  += __shfl_xor_sync(0xffffffffu, s,  o);
            s2 += __shfl_xor_sync(0xffffffffu, s2, o);
        }
        float mu   = s * (1.0f / DIM);
        float var  = s2 * (1.0f / DIM) - mu * mu;
        float rstd = rsqrtf(var + 1e-5f);
        #pragma unroll
        for (int j = 0; j < 4; j++) {
            int c = lane + j * 32;
            hs[r][c] = (xv[j] - mu) * rstd * gamma[c] + beta[c];
        }
    }
    __syncthreads();

    const int g  = t >> 8;               // 0=q, 1=k, 2=v
    const int tt = t & 255;
    const int c  = tt & 127;
    const int kh = tt >> 7;              // split-K half
    const float* W = (g == 0) ? Wq : (g == 1) ? Wk : Wv;
    const float* B = (g == 0) ? bq : (g == 1) ? bk : bv;
    float* O       = (g == 0) ? g_q : (g == 1) ? g_k : g_v;

    float acc[4];
    #pragma unroll
    for (int r = 0; r < 4; r++) acc[r] = 0.f;

    const int k0 = kh * 64;
    #pragma unroll 8
    for (int k = k0; k < k0 + 64; k += 4) {
        float w0 = W[(k+0)*DIM + c];
        float w1 = W[(k+1)*DIM + c];
        float w2 = W[(k+2)*DIM + c];
        float w3 = W[(k+3)*DIM + c];
        #pragma unroll
        for (int r = 0; r < 4; r++) {
            float4 hv = *(const float4*)&hs[r][k];
            acc[r] += hv.x*w0 + hv.y*w1 + hv.z*w2 + hv.w*w3;
        }
    }
    if (kh) {
        #pragma unroll
        for (int r = 0; r < 4; r++) part[g][r][c] = acc[r];
    }
    __syncthreads();
    if (!kh) {
        const float bb = B[c];
        const float sc = (g == 0) ? 0.25f : 1.0f;
        #pragma unroll
        for (int r = 0; r < 4; r++)
            O[(r0 + r) * DIM + c] = (acc[r] + part[g][r][c] + bb) * sc;
    }
}

// ---------------------------------------------------------------------------
// Kernel 2: fused edge-biased attention, softmax-free.
// grid 128, block 512 (16 warps = 4/SMSP). Warp w = 2r+g owns target row
// n = nb + r and head-group g (heads 4g..4g+3). Lane l handles source
// m = m0 + l for logits/exp; in the accumulate phase lane l owns output
// columns cv = 64g+2l (accv, float2) and edge dims e = (l&7)*2 of head
// h = 4g + (l>>3) (accs, float2). All p traffic stays within the warp.
// k/v/ef tiles double-buffered via cp.async.
// ---------------------------------------------------------------------------
__global__ void __launch_bounds__(512, 1) attn_kernel(
    const float* __restrict__ ef, const int* __restrict__ mask,
    const float* __restrict__ Wae, const float* __restrict__ bae,
    const float* __restrict__ Wve, const float* __restrict__ bve)
{
    extern __shared__ float sm[];
    float* q_s   = sm + OQ;
    float* wae_s = sm + OWAE;
    float* s_s   = sm + OS;
    float* p_s   = sm + OP;

    const int t = threadIdx.x;
    const int l = t & 31, w = t >> 5;
    const int r = w >> 1, g = w & 1;
    const int nb = blockIdx.x * BN;
    const int n  = nb + r;

    uint32_t smem_u32 = (uint32_t)__cvta_generic_to_shared(sm);

    // one-time loads
    for (int i = t; i < BN*DIM; i += 512) q_s[i] = g_q[nb*DIM + i];
    for (int i = t; i < ED*NH;  i += 512) wae_s[i] = Wae[i];

    float baer[4];
    #pragma unroll
    for (int hh = 0; hh < 4; hh++) baer[hh] = __ldg(&bae[4*g + hh]);

    // ---- tile staging via cp.async (512 threads) ----
    auto stage = [&](int m0, int buf) {
        const float* ksrc = g_k + m0 * DIM;
        const float* vsrc = g_v + m0 * DIM;
        uint32_t kd = smem_u32 + (uint32_t)(buf ? OK1 : OK0) * 4u;
        uint32_t vd = smem_u32 + (uint32_t)(buf ? OV1 : OV0) * 4u;
        #pragma unroll
        for (int j = 0; j < 2; j++) {
            int ch = t + j * 512;            // 0..1023 float4-chunks
            int row = ch >> 5, c4 = ch & 31;
            uint32_t off = (uint32_t)(row * KPAD + c4 * 4) * 4u;
            cpa16(kd + off, ksrc + row * DIM + c4 * 4);
            cpa16(vd + off, vsrc + row * DIM + c4 * 4);
        }
        uint32_t ed = smem_u32 + (uint32_t)(buf ? OE1 : OE0) * 4u;
        #pragma unroll
        for (int j = 0; j < 2; j++) {
            int ch = t + j * 512;
            int rr = ch >> 7, c = ch & 127;  // c = m*4 + e4
            int mi = c >> 2, e4 = c & 3;
            cpa16(ed + (uint32_t)((rr * BM + mi) * EFPAD + e4 * 4) * 4u,
                  ef + ((size_t)(nb + rr) * NN + m0 + mi) * ED + e4 * 4);
        }
    };

    stage(0, 0);
    cp_commit();

    float run_l[4] = {0.f, 0.f, 0.f, 0.f};
    float2 accv = make_float2(0.f, 0.f);
    float2 accs = make_float2(0.f, 0.f);

    const int hl   = l >> 3;             // local head in accumulate phase
    const int cv   = 64*g + 2*l;         // accv column pair
    const int eidx = (l & 7) * 2;        // accs edge-dim pair

    const int* mrow = mask + (size_t)n * NN;
    const float4* qv = (const float4*)(q_s + r * DIM + 64*g);

    cp_wait0();
    __syncthreads();   // tile 0 + q_s/wae_s ready

    for (int mt = 0; mt < NN / BM; mt++) {
        const int m0 = mt * BM;
        const int cur = mt & 1;
        float* k_s  = sm + (cur ? OK1 : OK0);
        float* v_s  = sm + (cur ? OV1 : OV0);
        float* ef_s = sm + (cur ? OE1 : OE0);

        if (mt + 1 < NN / BM) { stage(m0 + BM, cur ^ 1); cp_commit(); }

        const int mcur = mrow[m0 + l];

        // ---- logits for m = m0 + l, 4 heads of group g ----
        float lg[4];
        #pragma unroll
        for (int hh = 0; hh < 4; hh++) lg[hh] = baer[hh];
        {
            const float4* kv = (const float4*)(k_s + l * KPAD + 64*g);
            #pragma unroll
            for (int hh = 0; hh < 4; hh++) {
                float4 b0 = kv[hh*4+0], b1 = kv[hh*4+1];
                float4 b2 = kv[hh*4+2], b3 = kv[hh*4+3];
                float4 a0 = qv[hh*4+0], a1 = qv[hh*4+1];
                float4 a2 = qv[hh*4+2], a3 = qv[hh*4+3];
                lg[hh] += a0.x*b0.x + a0.y*b0.y + a0.z*b0.z + a0.w*b0.w
                        + a1.x*b1.x + a1.y*b1.y + a1.z*b1.z + a1.w*b1.w
                        + a2.x*b2.x + a2.y*b2.y + a2.z*b2.z + a2.w*b2.w
                        + a3.x*b3.x + a3.y*b3.y + a3.z*b3.z + a3.w*b3.w;
            }
        }
        // ---- edge bias: ef[n,m,:] @ Wae (4 heads) ----
        {
            const float4* efme = (const float4*)(ef_s + (r*BM + l) * EFPAD);
            float4 e4[4];
            e4[0]=efme[0]; e4[1]=efme[1]; e4[2]=efme[2]; e4[3]=efme[3];
            const float* ee = (const float*)e4;
            #pragma unroll
            for (int e = 0; e < 16; e++) {
                float evv = ee[e];
                #pragma unroll
                for (int hh = 0; hh < 4; hh++)
                    lg[hh] += evv * wae_s[e*8 + 4*g + hh];
            }
        }

        // ---- p = exp(logit) (0 if masked) ----
        #pragma unroll
        for (int hh = 0; hh < 4; hh++) {
            float p = mcur ? __expf(lg[hh]) : 0.f;
            p_s[(r*NH + 4*g + hh) * PSTR + l] = p;
            run_l[hh] += p;
        }
        __syncwarp();

        // ---- accumulate: lane owns (cv pair of v) and (h,e pair of ef) ----
        const float* prow = p_s + (r*NH + 4*g + hl) * PSTR;
        #pragma unroll
        for (int m4 = 0; m4 < 8; m4++) {
            float4 pq = *(const float4*)(prow + m4*4);
            const float pj[4] = {pq.x, pq.y, pq.z, pq.w};
            #pragma unroll
            for (int j = 0; j < 4; j++) {
                int mm = m4*4 + j;
                float2 vv = *(const float2*)(v_s + mm*KPAD + cv);
                float2 ee = *(const float2*)(ef_s + (r*BM + mm)*EFPAD + eidx);
                accv.x += pj[j]*vv.x; accv.y += pj[j]*vv.y;
                accs.x += pj[j]*ee.x; accs.y += pj[j]*ee.y;
            }
        }

        if (mt + 1 < NN / BM) cp_wait0();
        __syncthreads();   // all warps done with cur tile; next tile landed
    }

    // ---- denominators: warp-reduce the 4 heads of this group ----
    #pragma unroll
    for (int hh = 0; hh < 4; hh++) {
        float s = run_l[hh];
        #pragma unroll
        for (int o = 16; o; o >>= 1)
            s += __shfl_xor_sync(0xffffffffu, s, o);
        run_l[hh] = s;
    }
    float den = (hl == 0) ? run_l[0] : (hl == 1) ? run_l[1]
              : (hl == 2) ? run_l[2] : run_l[3];
    {
        float inv = 1.0f / den;
        accv.x *= inv; accv.y *= inv;
        accs.x *= inv; accs.y *= inv;
    }
    // Shat[r][h][e] (h = 4g+hl owned by this warp)
    *(float2*)(s_s + r*DIM + (4*g + hl)*16 + eidx) = accs;
    __syncwarp();

    float2 o = accv;
    {
        float2 b2 = *(const float2*)(bve + cv);
        o.x += b2.x; o.y += b2.y;
    }
    #pragma unroll
    for (int e = 0; e < 16; e++) {
        float sv = s_s[r*DIM + (4*g + hl)*16 + e];
        float2 wv = *(const float2*)(Wve + e*DIM + cv);
        o.x += sv*wv.x; o.y += sv*wv.y;
    }
    *(float2*)(g_att + (size_t)n*DIM + cv) = o;
}

// ---------------------------------------------------------------------------
// Kernel 3: output projection + residual. grid 256 (4 rows), block 256,
// split-K by 2.
// ---------------------------------------------------------------------------
__global__ void __launch_bounds__(256) out_proj_kernel(const float* __restrict__ x,
    const float* __restrict__ Wo, const float* __restrict__ bo,
    float* __restrict__ out)
{
    __shared__ float as[4][DIM];
    __shared__ float part[4][DIM];
    const int t = threadIdx.x;
    const int c = t & 127, half = t >> 7;
    const int r0 = blockIdx.x * 4;

    for (int i = t; i < 4*DIM; i += 256)
        as[i >> 7][i & 127] = g_att[r0*DIM + i];
    __syncthreads();

    float acc[4];
    #pragma unroll
    for (int r = 0; r < 4; r++) acc[r] = 0.f;

    const int k0 = half * 64;
    #pragma unroll 4
    for (int k = k0; k < k0 + 64; k += 4) {
        float w0 = Wo[(k+0)*DIM + c];
        float w1 = Wo[(k+1)*DIM + c];
        float w2 = Wo[(k+2)*DIM + c];
        float w3 = Wo[(k+3)*DIM + c];
        #pragma unroll
        for (int r = 0; r < 4; r++) {
            float4 hv = *(const float4*)&as[r][k];
            acc[r] += hv.x*w0 + hv.y*w1 + hv.z*w2 + hv.w*w3;
        }
    }
    if (half) {
        #pragma unroll
        for (int r = 0; r < 4; r++) part[r][c] = acc[r];
    }
    __syncthreads();
    if (!half) {
        const float bv = bo[c];
        #pragma unroll
        for (int r = 0; r < 4; r++)
            out[(r0+r)*DIM + c] = x[(r0+r)*DIM + c] + acc[r] + part[r][c] + bv;
    }
}

// ---------------------------------------------------------------------------
extern "C" void kernel_launch(void* const* d_in, const int* in_sizes, int n_in,
                              void* d_out, int out_size)
{
    const float* x    = (const float*)d_in[0];
    const float* ef   = (const float*)d_in[1];
    const int*   mask = (const int*)d_in[2];
    const float* Wq   = (const float*)d_in[3];
    const float* bq   = (const float*)d_in[4];
    const float* Wk   = (const float*)d_in[5];
    const float* bk   = (const float*)d_in[6];
    const float* Wv   = (const float*)d_in[7];
    const float* bv   = (const float*)d_in[8];
    const float* Wae  = (const float*)d_in[9];
    const float* bae  = (const float*)d_in[10];
    const float* Wve  = (const float*)d_in[11];
    const float* bve  = (const float*)d_in[12];
    const float* Wo   = (const float*)d_in[13];
    const float* bo   = (const float*)d_in[14];
    const float* gamma= (const float*)d_in[15];
    const float* beta = (const float*)d_in[16];
    float* out = (float*)d_out;

    cudaFuncSetAttribute(attn_kernel,
        cudaFuncAttributeMaxDynamicSharedMemorySize, SMEM_BYTES);

    ln_qkv_kernel<<<NN/4, 768>>>(x, Wq, bq, Wk, bk, Wv, bv, gamma, beta);
    attn_kernel<<<NN/BN, 512, SMEM_BYTES>>>(ef, mask, Wae, bae, Wve, bve);
    out_proj_kernel<<<NN/4, 256>>>(x, Wo, bo, out);
}

// round 16
// speedup vs baseline: 1.6382x; 1.1150x over previous
#include <cuda_runtime.h>
#include <cstdint>

#define NN   1024
#define DIM  128
#define NH   8
#define ED   16

#define BN   8      // target rows per CTA
#define BM   32     // source nodes per tile (one per lane)
#define KPAD 132    // k/v smem row stride (floats): conflict-free per-lane rows
#define EFPAD 20    // ef smem row stride (floats)
#define PSTR 36     // p smem per-(row,head) stride (floats)

// ---- attn smem layout (floats) ----
#define OQ    0
#define OWAE  (OQ   + BN*DIM)            // 1024
#define OS    (OWAE + ED*NH)             // 1152
#define OK0   (OS   + BN*DIM)            // 2176
#define OK1   (OK0  + BM*KPAD)           // 6400
#define OV0   (OK1  + BM*KPAD)           // 10624
#define OV1   (OV0  + BM*KPAD)           // 14848
#define OE0   (OV1  + BM*KPAD)           // 19072
#define OE1   (OE0  + BN*BM*EFPAD)       // 24192
#define OP    (OE1  + BN*BM*EFPAD)       // 29312
#define SMEM_FLOATS (OP + BN*NH*PSTR)    // 31616
#define SMEM_BYTES  (SMEM_FLOATS * 4)    // 126464

__device__ __align__(16) float g_q[NN*DIM];
__device__ __align__(16) float g_k[NN*DIM];
__device__ __align__(16) float g_v[NN*DIM];
__device__ __align__(16) float g_att[NN*DIM];

__device__ __forceinline__ void cpa16(uint32_t dst, const void* src) {
    asm volatile("cp.async.cg.shared.global [%0], [%1], 16;\n" :: "r"(dst), "l"(src));
}
__device__ __forceinline__ void cp_commit() { asm volatile("cp.async.commit_group;\n"); }
__device__ __forceinline__ void cp_wait0()  { asm volatile("cp.async.wait_group 0;\n"); }

// ---------------------------------------------------------------------------
// Kernel 1: pre-LayerNorm + Q/K/V projections, split-K.
// grid 256 (4 rows/CTA), block 768: warps 0-3 LN the 4 rows; then group
// g = t/256 computes projection g (0=q,1=k,2=v), with each half-warpgroup
// (kh = 0/1) covering half the K dimension. q pre-scaled by 0.25.
// ---------------------------------------------------------------------------
__global__ void __launch_bounds__(768) ln_qkv_kernel(const float* __restrict__ x,
    const float* __restrict__ Wq, const float* __restrict__ bq,
    const float* __restrict__ Wk, const float* __restrict__ bk,
    const float* __restrict__ Wv, const float* __restrict__ bv,
    const float* __restrict__ gamma, const float* __restrict__ beta)
{
    __shared__ float hs[4][DIM];
    __shared__ float part[3][4][DIM];
    const int t = threadIdx.x;
    const int lane = t & 31, wid = t >> 5;
    const int r0 = blockIdx.x * 4;

    if (wid < 4) {                       // one warp per row: LN
        const int r = wid;
        float xv[4], s = 0.f, s2 = 0.f;
        #pragma unroll
        for (int j = 0; j < 4; j++) {
            xv[j] = x[(r0 + r) * DIM + lane + j * 32];
            s += xv[j]; s2 += xv[j] * xv[j];
        }
        #pragma unroll
        for (int o = 16; o; o >>= 1) {
            s  += __shfl_xor_sync(0xffffffffu, s,  o);
            s2 += __shfl_xor_sync(0xffffffffu, s2, o);
        }
        float mu   = s * (1.0f / DIM);
        float var  = s2 * (1.0f / DIM) - mu * mu;
        float rstd = rsqrtf(var + 1e-5f);
        #pragma unroll
        for (int j = 0; j < 4; j++) {
            int c = lane + j * 32;
            hs[r][c] = (xv[j] - mu) * rstd * gamma[c] + beta[c];
        }
    }
    __syncthreads();

    const int g  = t >> 8;               // 0=q, 1=k, 2=v
    const int tt = t & 255;
    const int c  = tt & 127;
    const int kh = tt >> 7;              // split-K half
    const float* W = (g == 0) ? Wq : (g == 1) ? Wk : Wv;
    const float* B = (g == 0) ? bq : (g == 1) ? bk : bv;
    float* O       = (g == 0) ? g_q : (g == 1) ? g_k : g_v;

    float acc[4];
    #pragma unroll
    for (int r = 0; r < 4; r++) acc[r] = 0.f;

    const int k0 = kh * 64;
    #pragma unroll 8
    for (int k = k0; k < k0 + 64; k += 4) {
        float w0 = W[(k+0)*DIM + c];
        float w1 = W[(k+1)*DIM + c];
        float w2 = W[(k+2)*DIM + c];
        float w3 = W[(k+3)*DIM + c];
        #pragma unroll
        for (int r = 0; r < 4; r++) {
            float4 hv = *(const float4*)&hs[r][k];
            acc[r] += hv.x*w0 + hv.y*w1 + hv.z*w2 + hv.w*w3;
        }
    }
    if (kh) {
        #pragma unroll
        for (int r = 0; r < 4; r++) part[g][r][c] = acc[r];
    }
    __syncthreads();
    if (!kh) {
        const float bb = B[c];
        const float sc = (g == 0) ? 0.25f : 1.0f;
        #pragma unroll
        for (int r = 0; r < 4; r++)
            O[(r0 + r) * DIM + c] = (acc[r] + part[g][r][c] + bb) * sc;
    }
}

// ---------------------------------------------------------------------------
// Kernel 2: fused edge-biased attention, softmax-free.
// grid 128, block 512 (16 warps). Warp w = 2r+g owns target row n = nb + r
// and head-group g (heads 4g..4g+3). q for the warp's heads is HOISTED into
// 16 float4 registers before the tile loop (the compiler cannot hoist the
// smem loads itself due to possible aliasing with p_s stores); Wae bias is
// read as broadcast float4 rows. k/v/ef double-buffered via cp.async.
// ---------------------------------------------------------------------------
__global__ void __launch_bounds__(512, 1) attn_kernel(
    const float* __restrict__ ef, const int* __restrict__ mask,
    const float* __restrict__ Wae, const float* __restrict__ bae,
    const float* __restrict__ Wve, const float* __restrict__ bve)
{
    extern __shared__ float sm[];
    float* q_s   = sm + OQ;
    float* wae_s = sm + OWAE;
    float* s_s   = sm + OS;
    float* p_s   = sm + OP;

    const int t = threadIdx.x;
    const int l = t & 31, w = t >> 5;
    const int r = w >> 1, g = w & 1;
    const int nb = blockIdx.x * BN;
    const int n  = nb + r;

    uint32_t smem_u32 = (uint32_t)__cvta_generic_to_shared(sm);

    // one-time loads
    for (int i = t; i < BN*DIM; i += 512) q_s[i] = g_q[nb*DIM + i];
    for (int i = t; i < ED*NH;  i += 512) wae_s[i] = Wae[i];

    float baer[4];
    #pragma unroll
    for (int hh = 0; hh < 4; hh++) baer[hh] = __ldg(&bae[4*g + hh]);

    // ---- tile staging via cp.async (512 threads) ----
    auto stage = [&](int m0, int buf) {
        const float* ksrc = g_k + m0 * DIM;
        const float* vsrc = g_v + m0 * DIM;
        uint32_t kd = smem_u32 + (uint32_t)(buf ? OK1 : OK0) * 4u;
        uint32_t vd = smem_u32 + (uint32_t)(buf ? OV1 : OV0) * 4u;
        #pragma unroll
        for (int j = 0; j < 2; j++) {
            int ch = t + j * 512;            // 0..1023 float4-chunks
            int row = ch >> 5, c4 = ch & 31;
            uint32_t off = (uint32_t)(row * KPAD + c4 * 4) * 4u;
            cpa16(kd + off, ksrc + row * DIM + c4 * 4);
            cpa16(vd + off, vsrc + row * DIM + c4 * 4);
        }
        uint32_t ed = smem_u32 + (uint32_t)(buf ? OE1 : OE0) * 4u;
        #pragma unroll
        for (int j = 0; j < 2; j++) {
            int ch = t + j * 512;
            int rr = ch >> 7, c = ch & 127;  // c = m*4 + e4
            int mi = c >> 2, e4 = c & 3;
            cpa16(ed + (uint32_t)((rr * BM + mi) * EFPAD + e4 * 4) * 4u,
                  ef + ((size_t)(nb + rr) * NN + m0 + mi) * ED + e4 * 4);
        }
    };

    stage(0, 0);
    cp_commit();

    float run_l[4] = {0.f, 0.f, 0.f, 0.f};
    float2 accv = make_float2(0.f, 0.f);
    float2 accs = make_float2(0.f, 0.f);

    const int hl   = l >> 3;             // local head in accumulate phase
    const int cv   = 64*g + 2*l;         // accv column pair
    const int eidx = (l & 7) * 2;        // accs edge-dim pair

    const int* mrow = mask + (size_t)n * NN;

    cp_wait0();
    __syncthreads();   // tile 0 + q_s/wae_s ready

    // ---- hoist q for this warp's (row, head-group) into registers ----
    float4 qreg[16];
    {
        const float4* qv = (const float4*)(q_s + r * DIM + 64*g);
        #pragma unroll
        for (int i = 0; i < 16; i++) qreg[i] = qv[i];
    }

    for (int mt = 0; mt < NN / BM; mt++) {
        const int m0 = mt * BM;
        const int cur = mt & 1;
        float* k_s  = sm + (cur ? OK1 : OK0);
        float* v_s  = sm + (cur ? OV1 : OV0);
        float* ef_s = sm + (cur ? OE1 : OE0);

        if (mt + 1 < NN / BM) { stage(m0 + BM, cur ^ 1); cp_commit(); }

        const int mcur = mrow[m0 + l];

        // ---- logits for m = m0 + l, 4 heads of group g (q in regs) ----
        float lg[4];
        #pragma unroll
        for (int hh = 0; hh < 4; hh++) lg[hh] = baer[hh];
        {
            const float4* kv = (const float4*)(k_s + l * KPAD + 64*g);
            #pragma unroll
            for (int hh = 0; hh < 4; hh++) {
                float4 b0 = kv[hh*4+0], b1 = kv[hh*4+1];
                float4 b2 = kv[hh*4+2], b3 = kv[hh*4+3];
                float4 a0 = qreg[hh*4+0], a1 = qreg[hh*4+1];
                float4 a2 = qreg[hh*4+2], a3 = qreg[hh*4+3];
                lg[hh] += a0.x*b0.x + a0.y*b0.y + a0.z*b0.z + a0.w*b0.w
                        + a1.x*b1.x + a1.y*b1.y + a1.z*b1.z + a1.w*b1.w
                        + a2.x*b2.x + a2.y*b2.y + a2.z*b2.z + a2.w*b2.w
                        + a3.x*b3.x + a3.y*b3.y + a3.z*b3.z + a3.w*b3.w;
            }
        }
        // ---- edge bias: ef[n,m,:] @ Wae (4 heads), Wae as float4 rows ----
        {
            const float4* efme = (const float4*)(ef_s + (r*BM + l) * EFPAD);
            float4 e4[4];
            e4[0]=efme[0]; e4[1]=efme[1]; e4[2]=efme[2]; e4[3]=efme[3];
            const float* ee = (const float*)e4;
            #pragma unroll
            for (int e = 0; e < 16; e++) {
                float evv = ee[e];
                float4 ww = *(const float4*)&wae_s[e*8 + 4*g];
                lg[0] += evv * ww.x;
                lg[1] += evv * ww.y;
                lg[2] += evv * ww.z;
                lg[3] += evv * ww.w;
            }
        }

        // ---- p = exp(logit) (0 if masked) ----
        #pragma unroll
        for (int hh = 0; hh < 4; hh++) {
            float p = mcur ? __expf(lg[hh]) : 0.f;
            p_s[(r*NH + 4*g + hh) * PSTR + l] = p;
            run_l[hh] += p;
        }
        __syncwarp();

        // ---- accumulate: lane owns (cv pair of v) and (h,e pair of ef) ----
        const float* prow = p_s + (r*NH + 4*g + hl) * PSTR;
        #pragma unroll
        for (int m4 = 0; m4 < 8; m4++) {
            float4 pq = *(const float4*)(prow + m4*4);
            const float pj[4] = {pq.x, pq.y, pq.z, pq.w};
            #pragma unroll
            for (int j = 0; j < 4; j++) {
                int mm = m4*4 + j;
                float2 vv = *(const float2*)(v_s + mm*KPAD + cv);
                float2 ee = *(const float2*)(ef_s + (r*BM + mm)*EFPAD + eidx);
                accv.x += pj[j]*vv.x; accv.y += pj[j]*vv.y;
                accs.x += pj[j]*ee.x; accs.y += pj[j]*ee.y;
            }
        }

        if (mt + 1 < NN / BM) cp_wait0();
        __syncthreads();   // all warps done with cur tile; next tile landed
    }

    // ---- denominators: warp-reduce the 4 heads of this group ----
    #pragma unroll
    for (int hh = 0; hh < 4; hh++) {
        float s = run_l[hh];
        #pragma unroll
        for (int o = 16; o; o >>= 1)
            s += __shfl_xor_sync(0xffffffffu, s, o);
        run_l[hh] = s;
    }
    float den = (hl == 0) ? run_l[0] : (hl == 1) ? run_l[1]
              : (hl == 2) ? run_l[2] : run_l[3];
    {
        float inv = 1.0f / den;
        accv.x *= inv; accv.y *= inv;
        accs.x *= inv; accs.y *= inv;
    }
    // Shat[r][h][e] (h = 4g+hl owned by this warp)
    *(float2*)(s_s + r*DIM + (4*g + hl)*16 + eidx) = accs;
    __syncwarp();

    float2 o = accv;
    {
        float2 b2 = *(const float2*)(bve + cv);
        o.x += b2.x; o.y += b2.y;
    }
    #pragma unroll
    for (int e = 0; e < 16; e++) {
        float sv = s_s[r*DIM + (4*g + hl)*16 + e];
        float2 wv = *(const float2*)(Wve + e*DIM + cv);
        o.x += sv*wv.x; o.y += sv*wv.y;
    }
    *(float2*)(g_att + (size_t)n*DIM + cv) = o;
}

// ---------------------------------------------------------------------------
// Kernel 3: output projection + residual. grid 256 (4 rows), block 256,
// split-K by 2.
// ---------------------------------------------------------------------------
__global__ void __launch_bounds__(256) out_proj_kernel(const float* __restrict__ x,
    const float* __restrict__ Wo, const float* __restrict__ bo,
    float* __restrict__ out)
{
    __shared__ float as[4][DIM];
    __shared__ float part[4][DIM];
    const int t = threadIdx.x;
    const int c = t & 127, half = t >> 7;
    const int r0 = blockIdx.x * 4;

    for (int i = t; i < 4*DIM; i += 256)
        as[i >> 7][i & 127] = g_att[r0*DIM + i];
    __syncthreads();

    float acc[4];
    #pragma unroll
    for (int r = 0; r < 4; r++) acc[r] = 0.f;

    const int k0 = half * 64;
    #pragma unroll 4
    for (int k = k0; k < k0 + 64; k += 4) {
        float w0 = Wo[(k+0)*DIM + c];
        float w1 = Wo[(k+1)*DIM + c];
        float w2 = Wo[(k+2)*DIM + c];
        float w3 = Wo[(k+3)*DIM + c];
        #pragma unroll
        for (int r = 0; r < 4; r++) {
            float4 hv = *(const float4*)&as[r][k];
            acc[r] += hv.x*w0 + hv.y*w1 + hv.z*w2 + hv.w*w3;
        }
    }
    if (half) {
        #pragma unroll
        for (int r = 0; r < 4; r++) part[r][c] = acc[r];
    }
    __syncthreads();
    if (!half) {
        const float bv = bo[c];
        #pragma unroll
        for (int r = 0; r < 4; r++)
            out[(r0+r)*DIM + c] = x[(r0+r)*DIM + c] + acc[r] + part[r][c] + bv;
    }
}

// ---------------------------------------------------------------------------
extern "C" void kernel_launch(void* const* d_in, const int* in_sizes, int n_in,
                              void* d_out, int out_size)
{
    const float* x    = (const float*)d_in[0];
    const float* ef   = (const float*)d_in[1];
    const int*   mask = (const int*)d_in[2];
    const float* Wq   = (const float*)d_in[3];
    const float* bq   = (const float*)d_in[4];
    const float* Wk   = (const float*)d_in[5];
    const float* bk   = (const float*)d_in[6];
    const float* Wv   = (const float*)d_in[7];
    const float* bv   = (const float*)d_in[8];
    const float* Wae  = (const float*)d_in[9];
    const float* bae  = (const float*)d_in[10];
    const float* Wve  = (const float*)d_in[11];
    const float* bve  = (const float*)d_in[12];
    const float* Wo   = (const float*)d_in[13];
    const float* bo   = (const float*)d_in[14];
    const float* gamma= (const float*)d_in[15];
    const float* beta = (const float*)d_in[16];
    float* out = (float*)d_out;

    cudaFuncSetAttribute(attn_kernel,
        cudaFuncAttributeMaxDynamicSharedMemorySize, SMEM_BYTES);

    ln_qkv_kernel<<<NN/4, 768>>>(x, Wq, bq, Wk, bk, Wv, bv, gamma, beta);
    attn_kernel<<<NN/BN, 512, SMEM_BYTES>>>(ef, mask, Wae, bae, Wve, bve);
    out_proj_kernel<<<NN/4, 256>>>(x, Wo, bo, out);
}